// round 1
// baseline (speedup 1.0000x reference)
#include <cuda_runtime.h>
#include <cstdint>

#define BB 4
#define TT 2048
#define DD 512
#define HH 8
#define DKK 64

// Scratch (head-split layout: [b,h,t,dk])
__device__ float g_q[BB*HH*TT*DKK];
__device__ float g_k[BB*HH*TT*DKK];
__device__ float g_v[BB*HH*TT*DKK];
__device__ float g_x[BB*HH*TT*DKK];

// ---------------------------------------------------------------------------
// QKV projection: out[b,h,t,dk] = sum_k in[m,k] * W[n,k] + bias[n]
// m = b*T+t (8192), n = h*64+dk (512). 64x64 tile, 4x4 per thread, BK=16.
// ---------------------------------------------------------------------------
__global__ __launch_bounds__(256) void qkv_proj_kernel(
    const float* __restrict__ q_in, const float* __restrict__ k_in,
    const float* __restrict__ v_in,
    const float* __restrict__ Wq, const float* __restrict__ bq,
    const float* __restrict__ Wk, const float* __restrict__ bk,
    const float* __restrict__ Wv, const float* __restrict__ bv)
{
    const int which = blockIdx.z;
    const float* A    = which == 0 ? q_in : (which == 1 ? k_in : v_in);
    const float* W    = which == 0 ? Wq   : (which == 1 ? Wk   : Wv);
    const float* bias = which == 0 ? bq   : (which == 1 ? bk   : bv);
    float* outp       = which == 0 ? g_q  : (which == 1 ? g_k  : g_v);

    __shared__ float sA[16][64];   // [k][m] transposed
    __shared__ float sB[16][64];   // [k][n] transposed

    const int tid = threadIdx.x;
    const int tx = tid & 15, ty = tid >> 4;
    const int m0 = blockIdx.y * 64;
    const int n0 = blockIdx.x * 64;
    const int lrow = tid >> 2;        // 0..63
    const int lk   = (tid & 3) * 4;   // 0,4,8,12

    float acc[4][4] = {};

    for (int k0 = 0; k0 < 512; k0 += 16) {
        float4 av = *reinterpret_cast<const float4*>(&A[(m0 + lrow) * 512 + k0 + lk]);
        float4 wv = *reinterpret_cast<const float4*>(&W[(n0 + lrow) * 512 + k0 + lk]);
        __syncthreads();
        sA[lk + 0][lrow] = av.x; sA[lk + 1][lrow] = av.y;
        sA[lk + 2][lrow] = av.z; sA[lk + 3][lrow] = av.w;
        sB[lk + 0][lrow] = wv.x; sB[lk + 1][lrow] = wv.y;
        sB[lk + 2][lrow] = wv.z; sB[lk + 3][lrow] = wv.w;
        __syncthreads();
        #pragma unroll
        for (int kk = 0; kk < 16; kk++) {
            float4 a = *reinterpret_cast<const float4*>(&sA[kk][ty * 4]);
            float4 b = *reinterpret_cast<const float4*>(&sB[kk][tx * 4]);
            acc[0][0] += a.x * b.x; acc[0][1] += a.x * b.y; acc[0][2] += a.x * b.z; acc[0][3] += a.x * b.w;
            acc[1][0] += a.y * b.x; acc[1][1] += a.y * b.y; acc[1][2] += a.y * b.z; acc[1][3] += a.y * b.w;
            acc[2][0] += a.z * b.x; acc[2][1] += a.z * b.y; acc[2][2] += a.z * b.z; acc[2][3] += a.z * b.w;
            acc[3][0] += a.w * b.x; acc[3][1] += a.w * b.y; acc[3][2] += a.w * b.z; acc[3][3] += a.w * b.w;
        }
    }

    const int n = n0 + tx * 4;           // aligned 4, stays within one head
    const int h_ = n >> 6, dk_ = n & 63;
    float4 bvv = *reinterpret_cast<const float4*>(&bias[n]);
    #pragma unroll
    for (int i = 0; i < 4; i++) {
        const int m = m0 + ty * 4 + i;
        const int b_ = m >> 11, t_ = m & 2047;
        float4 o;
        o.x = acc[i][0] + bvv.x; o.y = acc[i][1] + bvv.y;
        o.z = acc[i][2] + bvv.z; o.w = acc[i][3] + bvv.w;
        *reinterpret_cast<float4*>(
            &outp[(((size_t)b_ * HH + h_) * TT + t_) * DKK + dk_]) = o;
    }
}

// ---------------------------------------------------------------------------
// Fused attention: per (b,h, 64-row q tile). Online softmax over 64-col KV tiles.
// Writes sigmoid(scores) to sig, normalized attention output to g_x.
// ---------------------------------------------------------------------------
__global__ __launch_bounds__(256) void attn_kernel(
    const int* __restrict__ mask, float* __restrict__ sig)
{
    __shared__ float sQ[64][64];   // [dk][qrow] transposed
    __shared__ float sKP[64][64];  // K: [dk][kvcol] transposed; then P: [qrow][kvcol]
    __shared__ float sV[64][64];   // [kvrow][dk] natural

    const int tid = threadIdx.x;
    const int tx = tid & 15, ty = tid >> 4;
    const int bh = blockIdx.y;
    const int b_ = bh >> 3;
    const int q0 = blockIdx.x * 64;

    const float* Qg = g_q + (size_t)bh * TT * DKK;
    const float* Kg = g_k + (size_t)bh * TT * DKK;
    const float* Vg = g_v + (size_t)bh * TT * DKK;
    float* sigbh = sig + (size_t)bh * TT * TT;

    // Load Q tile transposed
    #pragma unroll
    for (int r = 0; r < 4; r++) {
        int id = tid + r * 256;
        int row = id >> 4;
        int c4 = (id & 15) * 4;
        float4 v = *reinterpret_cast<const float4*>(&Qg[(q0 + row) * 64 + c4]);
        sQ[c4 + 0][row] = v.x; sQ[c4 + 1][row] = v.y;
        sQ[c4 + 2][row] = v.z; sQ[c4 + 3][row] = v.w;
    }

    float m_run[4], l_run[4];
    float o[4][4] = {};
    #pragma unroll
    for (int i = 0; i < 4; i++) { m_run[i] = -1e30f; l_run[i] = 0.0f; }

    const float scale = 0.125f;  // 1/sqrt(64)

    for (int kv0 = 0; kv0 < TT; kv0 += 64) {
        __syncthreads();  // prev iteration done reading sKP/sV
        #pragma unroll
        for (int r = 0; r < 4; r++) {
            int id = tid + r * 256;
            int row = id >> 4;
            int c4 = (id & 15) * 4;
            float4 kv = *reinterpret_cast<const float4*>(&Kg[(kv0 + row) * 64 + c4]);
            sKP[c4 + 0][row] = kv.x; sKP[c4 + 1][row] = kv.y;
            sKP[c4 + 2][row] = kv.z; sKP[c4 + 3][row] = kv.w;
            float4 vv = *reinterpret_cast<const float4*>(&Vg[(kv0 + row) * 64 + c4]);
            *reinterpret_cast<float4*>(&sV[row][c4]) = vv;
        }
        __syncthreads();

        // S = Q @ K^T
        float s[4][4] = {};
        #pragma unroll
        for (int kk = 0; kk < 64; kk++) {
            float4 a = *reinterpret_cast<const float4*>(&sQ[kk][ty * 4]);
            float4 b = *reinterpret_cast<const float4*>(&sKP[kk][tx * 4]);
            s[0][0] += a.x * b.x; s[0][1] += a.x * b.y; s[0][2] += a.x * b.z; s[0][3] += a.x * b.w;
            s[1][0] += a.y * b.x; s[1][1] += a.y * b.y; s[1][2] += a.y * b.z; s[1][3] += a.y * b.w;
            s[2][0] += a.z * b.x; s[2][1] += a.z * b.y; s[2][2] += a.z * b.z; s[2][3] += a.z * b.w;
            s[3][0] += a.w * b.x; s[3][1] += a.w * b.y; s[3][2] += a.w * b.z; s[3][3] += a.w * b.w;
        }

        // scale + mask
        int mk[4];
        #pragma unroll
        for (int j = 0; j < 4; j++)
            mk[j] = __ldg(&mask[b_ * TT + kv0 + tx * 4 + j]);
        #pragma unroll
        for (int i = 0; i < 4; i++)
            #pragma unroll
            for (int j = 0; j < 4; j++) {
                float v = s[i][j] * scale;
                s[i][j] = (mk[j] == 0) ? -1e9f : v;
            }

        // sigmoid store (coalesced float4 per row)
        #pragma unroll
        for (int i = 0; i < 4; i++) {
            float4 sg;
            sg.x = 1.0f / (1.0f + __expf(-s[i][0]));
            sg.y = 1.0f / (1.0f + __expf(-s[i][1]));
            sg.z = 1.0f / (1.0f + __expf(-s[i][2]));
            sg.w = 1.0f / (1.0f + __expf(-s[i][3]));
            *reinterpret_cast<float4*>(
                &sigbh[(size_t)(q0 + ty * 4 + i) * TT + kv0 + tx * 4]) = sg;
        }

        // online softmax: row max + exp + row sum (reduce across 16-lane group)
        float mnew[4], psum[4];
        #pragma unroll
        for (int i = 0; i < 4; i++) {
            float tm = fmaxf(fmaxf(s[i][0], s[i][1]), fmaxf(s[i][2], s[i][3]));
            #pragma unroll
            for (int off = 8; off; off >>= 1)
                tm = fmaxf(tm, __shfl_xor_sync(0xffffffffu, tm, off));
            mnew[i] = fmaxf(m_run[i], tm);
            float p0 = __expf(s[i][0] - mnew[i]);
            float p1 = __expf(s[i][1] - mnew[i]);
            float p2 = __expf(s[i][2] - mnew[i]);
            float p3 = __expf(s[i][3] - mnew[i]);
            s[i][0] = p0; s[i][1] = p1; s[i][2] = p2; s[i][3] = p3;
            float ps = p0 + p1 + p2 + p3;
            #pragma unroll
            for (int off = 8; off; off >>= 1)
                ps += __shfl_xor_sync(0xffffffffu, ps, off);
            psum[i] = ps;
        }

        __syncthreads();  // everyone done reading sKP as K
        #pragma unroll
        for (int i = 0; i < 4; i++) {
            *reinterpret_cast<float4*>(&sKP[ty * 4 + i][tx * 4]) =
                make_float4(s[i][0], s[i][1], s[i][2], s[i][3]);
        }
        __syncthreads();

        // rescale accumulators, update m,l
        #pragma unroll
        for (int i = 0; i < 4; i++) {
            float corr = __expf(m_run[i] - mnew[i]);
            l_run[i] = l_run[i] * corr + psum[i];
            m_run[i] = mnew[i];
            o[i][0] *= corr; o[i][1] *= corr; o[i][2] *= corr; o[i][3] *= corr;
        }

        // O += P @ V
        #pragma unroll
        for (int kk = 0; kk < 64; kk++) {
            float4 vv = *reinterpret_cast<const float4*>(&sV[kk][tx * 4]);
            float p0 = sKP[ty * 4 + 0][kk];
            float p1 = sKP[ty * 4 + 1][kk];
            float p2 = sKP[ty * 4 + 2][kk];
            float p3 = sKP[ty * 4 + 3][kk];
            o[0][0] += p0 * vv.x; o[0][1] += p0 * vv.y; o[0][2] += p0 * vv.z; o[0][3] += p0 * vv.w;
            o[1][0] += p1 * vv.x; o[1][1] += p1 * vv.y; o[1][2] += p1 * vv.z; o[1][3] += p1 * vv.w;
            o[2][0] += p2 * vv.x; o[2][1] += p2 * vv.y; o[2][2] += p2 * vv.z; o[2][3] += p2 * vv.w;
            o[3][0] += p3 * vv.x; o[3][1] += p3 * vv.y; o[3][2] += p3 * vv.z; o[3][3] += p3 * vv.w;
        }
    }

    // normalize + store to g_x
    #pragma unroll
    for (int i = 0; i < 4; i++) {
        float inv = 1.0f / l_run[i];
        float4 ov = make_float4(o[i][0] * inv, o[i][1] * inv,
                                o[i][2] * inv, o[i][3] * inv);
        *reinterpret_cast<float4*>(
            &g_x[((size_t)bh * TT + q0 + ty * 4 + i) * DKK + tx * 4]) = ov;
    }
}

// ---------------------------------------------------------------------------
// Output projection: out[m,n] = sum_k x[m,k] * Wo[n,k] + bo[n]
// x read from head-split g_x.
// ---------------------------------------------------------------------------
__global__ __launch_bounds__(256) void out_proj_kernel(
    const float* __restrict__ Wo, const float* __restrict__ bo,
    float* __restrict__ outp)
{
    __shared__ float sA[16][64];
    __shared__ float sB[16][64];

    const int tid = threadIdx.x;
    const int tx = tid & 15, ty = tid >> 4;
    const int m0 = blockIdx.y * 64;
    const int n0 = blockIdx.x * 64;
    const int lrow = tid >> 2;
    const int lk   = (tid & 3) * 4;

    float acc[4][4] = {};

    const int m = m0 + lrow;
    const int b_ = m >> 11, t_ = m & 2047;

    for (int k0 = 0; k0 < 512; k0 += 16) {
        const int k = k0 + lk;
        const int h_ = k >> 6, dk_ = k & 63;
        float4 av = *reinterpret_cast<const float4*>(
            &g_x[(((size_t)b_ * HH + h_) * TT + t_) * DKK + dk_]);
        float4 wv = *reinterpret_cast<const float4*>(&Wo[(n0 + lrow) * 512 + k]);
        __syncthreads();
        sA[lk + 0][lrow] = av.x; sA[lk + 1][lrow] = av.y;
        sA[lk + 2][lrow] = av.z; sA[lk + 3][lrow] = av.w;
        sB[lk + 0][lrow] = wv.x; sB[lk + 1][lrow] = wv.y;
        sB[lk + 2][lrow] = wv.z; sB[lk + 3][lrow] = wv.w;
        __syncthreads();
        #pragma unroll
        for (int kk = 0; kk < 16; kk++) {
            float4 a = *reinterpret_cast<const float4*>(&sA[kk][ty * 4]);
            float4 b = *reinterpret_cast<const float4*>(&sB[kk][tx * 4]);
            acc[0][0] += a.x * b.x; acc[0][1] += a.x * b.y; acc[0][2] += a.x * b.z; acc[0][3] += a.x * b.w;
            acc[1][0] += a.y * b.x; acc[1][1] += a.y * b.y; acc[1][2] += a.y * b.z; acc[1][3] += a.y * b.w;
            acc[2][0] += a.z * b.x; acc[2][1] += a.z * b.y; acc[2][2] += a.z * b.z; acc[2][3] += a.z * b.w;
            acc[3][0] += a.w * b.x; acc[3][1] += a.w * b.y; acc[3][2] += a.w * b.z; acc[3][3] += a.w * b.w;
        }
    }

    const int n = n0 + tx * 4;
    float4 bvv = *reinterpret_cast<const float4*>(&bo[n]);
    #pragma unroll
    for (int i = 0; i < 4; i++) {
        const int mm = m0 + ty * 4 + i;
        float4 ov;
        ov.x = acc[i][0] + bvv.x; ov.y = acc[i][1] + bvv.y;
        ov.z = acc[i][2] + bvv.z; ov.w = acc[i][3] + bvv.w;
        *reinterpret_cast<float4*>(&outp[(size_t)mm * 512 + n]) = ov;
    }
}

// ---------------------------------------------------------------------------
extern "C" void kernel_launch(void* const* d_in, const int* in_sizes, int n_in,
                              void* d_out, int out_size)
{
    const float* query = (const float*)d_in[0];
    const float* key   = (const float*)d_in[1];
    const float* value = (const float*)d_in[2];
    const int*   mask  = (const int*)d_in[3];
    const float* Wq = (const float*)d_in[4];
    const float* bq = (const float*)d_in[5];
    const float* Wk = (const float*)d_in[6];
    const float* bk = (const float*)d_in[7];
    const float* Wv = (const float*)d_in[8];
    const float* bv = (const float*)d_in[9];
    const float* Wo = (const float*)d_in[10];
    const float* bo = (const float*)d_in[11];

    float* out0 = (float*)d_out;                       // (B,T,D)
    float* sig  = out0 + (size_t)BB * TT * DD;         // (B,H,T,T)

    qkv_proj_kernel<<<dim3(8, 128, 3), 256>>>(query, key, value,
                                              Wq, bq, Wk, bk, Wv, bv);
    attn_kernel<<<dim3(TT / 64, BB * HH), 256>>>(mask, sig);
    out_proj_kernel<<<dim3(8, 128), 256>>>(Wo, bo, out0);
}

// round 2
// speedup vs baseline: 1.0017x; 1.0017x over previous
#include <cuda_runtime.h>
#include <cstdint>

#define BB 4
#define TT 2048
#define DD 512
#define HH 8
#define DKK 64

// Scratch (head-split layout: [b,h,t,dk])
__device__ float g_q[BB*HH*TT*DKK];
__device__ float g_k[BB*HH*TT*DKK];
__device__ float g_v[BB*HH*TT*DKK];
__device__ float g_x[BB*HH*TT*DKK];

// ---------------------------------------------------------------------------
// QKV projection: out[b,h,t,dk] = sum_k in[m,k] * W[n,k] + bias[n]
// m = b*T+t (8192), n = h*64+dk (512). 64x64 tile, 4x4 per thread, BK=16.
// ---------------------------------------------------------------------------
__global__ __launch_bounds__(256) void qkv_proj_kernel(
    const float* __restrict__ q_in, const float* __restrict__ k_in,
    const float* __restrict__ v_in,
    const float* __restrict__ Wq, const float* __restrict__ bq,
    const float* __restrict__ Wk, const float* __restrict__ bk,
    const float* __restrict__ Wv, const float* __restrict__ bv)
{
    const int which = blockIdx.z;
    const float* A    = which == 0 ? q_in : (which == 1 ? k_in : v_in);
    const float* W    = which == 0 ? Wq   : (which == 1 ? Wk   : Wv);
    const float* bias = which == 0 ? bq   : (which == 1 ? bk   : bv);
    float* outp       = which == 0 ? g_q  : (which == 1 ? g_k  : g_v);

    __shared__ float sA[16][64];   // [k][m] transposed
    __shared__ float sB[16][64];   // [k][n] transposed

    const int tid = threadIdx.x;
    const int tx = tid & 15, ty = tid >> 4;
    const int m0 = blockIdx.y * 64;
    const int n0 = blockIdx.x * 64;
    const int lrow = tid >> 2;        // 0..63
    const int lk   = (tid & 3) * 4;   // 0,4,8,12

    float acc[4][4] = {};

    for (int k0 = 0; k0 < 512; k0 += 16) {
        float4 av = *reinterpret_cast<const float4*>(&A[(m0 + lrow) * 512 + k0 + lk]);
        float4 wv = *reinterpret_cast<const float4*>(&W[(n0 + lrow) * 512 + k0 + lk]);
        __syncthreads();
        sA[lk + 0][lrow] = av.x; sA[lk + 1][lrow] = av.y;
        sA[lk + 2][lrow] = av.z; sA[lk + 3][lrow] = av.w;
        sB[lk + 0][lrow] = wv.x; sB[lk + 1][lrow] = wv.y;
        sB[lk + 2][lrow] = wv.z; sB[lk + 3][lrow] = wv.w;
        __syncthreads();
        #pragma unroll
        for (int kk = 0; kk < 16; kk++) {
            float4 a = *reinterpret_cast<const float4*>(&sA[kk][ty * 4]);
            float4 b = *reinterpret_cast<const float4*>(&sB[kk][tx * 4]);
            acc[0][0] += a.x * b.x; acc[0][1] += a.x * b.y; acc[0][2] += a.x * b.z; acc[0][3] += a.x * b.w;
            acc[1][0] += a.y * b.x; acc[1][1] += a.y * b.y; acc[1][2] += a.y * b.z; acc[1][3] += a.y * b.w;
            acc[2][0] += a.z * b.x; acc[2][1] += a.z * b.y; acc[2][2] += a.z * b.z; acc[2][3] += a.z * b.w;
            acc[3][0] += a.w * b.x; acc[3][1] += a.w * b.y; acc[3][2] += a.w * b.z; acc[3][3] += a.w * b.w;
        }
    }

    const int n = n0 + tx * 4;           // aligned 4, stays within one head
    const int h_ = n >> 6, dk_ = n & 63;
    float4 bvv = *reinterpret_cast<const float4*>(&bias[n]);
    #pragma unroll
    for (int i = 0; i < 4; i++) {
        const int m = m0 + ty * 4 + i;
        const int b_ = m >> 11, t_ = m & 2047;
        float4 o;
        o.x = acc[i][0] + bvv.x; o.y = acc[i][1] + bvv.y;
        o.z = acc[i][2] + bvv.z; o.w = acc[i][3] + bvv.w;
        *reinterpret_cast<float4*>(
            &outp[(((size_t)b_ * HH + h_) * TT + t_) * DKK + dk_]) = o;
    }
}

// ---------------------------------------------------------------------------
// Fused attention: per (b,h, 64-row q tile). Online softmax over 64-col KV tiles.
// Writes sigmoid(scores) to sig, normalized attention output to g_x.
// ---------------------------------------------------------------------------
__global__ __launch_bounds__(256) void attn_kernel(
    const int* __restrict__ mask, float* __restrict__ sig)
{
    __shared__ float sQ[64][64];   // [dk][qrow] transposed
    __shared__ float sKP[64][64];  // K: [dk][kvcol] transposed; then P: [qrow][kvcol]
    __shared__ float sV[64][64];   // [kvrow][dk] natural

    const int tid = threadIdx.x;
    const int tx = tid & 15, ty = tid >> 4;
    const int bh = blockIdx.y;
    const int b_ = bh >> 3;
    const int q0 = blockIdx.x * 64;

    const float* Qg = g_q + (size_t)bh * TT * DKK;
    const float* Kg = g_k + (size_t)bh * TT * DKK;
    const float* Vg = g_v + (size_t)bh * TT * DKK;
    float* sigbh = sig + (size_t)bh * TT * TT;

    // Load Q tile transposed
    #pragma unroll
    for (int r = 0; r < 4; r++) {
        int id = tid + r * 256;
        int row = id >> 4;
        int c4 = (id & 15) * 4;
        float4 v = *reinterpret_cast<const float4*>(&Qg[(q0 + row) * 64 + c4]);
        sQ[c4 + 0][row] = v.x; sQ[c4 + 1][row] = v.y;
        sQ[c4 + 2][row] = v.z; sQ[c4 + 3][row] = v.w;
    }

    float m_run[4], l_run[4];
    float o[4][4] = {};
    #pragma unroll
    for (int i = 0; i < 4; i++) { m_run[i] = -1e30f; l_run[i] = 0.0f; }

    const float scale = 0.125f;  // 1/sqrt(64)

    for (int kv0 = 0; kv0 < TT; kv0 += 64) {
        __syncthreads();  // prev iteration done reading sKP/sV
        #pragma unroll
        for (int r = 0; r < 4; r++) {
            int id = tid + r * 256;
            int row = id >> 4;
            int c4 = (id & 15) * 4;
            float4 kv = *reinterpret_cast<const float4*>(&Kg[(kv0 + row) * 64 + c4]);
            sKP[c4 + 0][row] = kv.x; sKP[c4 + 1][row] = kv.y;
            sKP[c4 + 2][row] = kv.z; sKP[c4 + 3][row] = kv.w;
            float4 vv = *reinterpret_cast<const float4*>(&Vg[(kv0 + row) * 64 + c4]);
            *reinterpret_cast<float4*>(&sV[row][c4]) = vv;
        }
        __syncthreads();

        // S = Q @ K^T
        float s[4][4] = {};
        #pragma unroll
        for (int kk = 0; kk < 64; kk++) {
            float4 a = *reinterpret_cast<const float4*>(&sQ[kk][ty * 4]);
            float4 b = *reinterpret_cast<const float4*>(&sKP[kk][tx * 4]);
            s[0][0] += a.x * b.x; s[0][1] += a.x * b.y; s[0][2] += a.x * b.z; s[0][3] += a.x * b.w;
            s[1][0] += a.y * b.x; s[1][1] += a.y * b.y; s[1][2] += a.y * b.z; s[1][3] += a.y * b.w;
            s[2][0] += a.z * b.x; s[2][1] += a.z * b.y; s[2][2] += a.z * b.z; s[2][3] += a.z * b.w;
            s[3][0] += a.w * b.x; s[3][1] += a.w * b.y; s[3][2] += a.w * b.z; s[3][3] += a.w * b.w;
        }

        // scale + mask
        int mk[4];
        #pragma unroll
        for (int j = 0; j < 4; j++)
            mk[j] = __ldg(&mask[b_ * TT + kv0 + tx * 4 + j]);
        #pragma unroll
        for (int i = 0; i < 4; i++)
            #pragma unroll
            for (int j = 0; j < 4; j++) {
                float v = s[i][j] * scale;
                s[i][j] = (mk[j] == 0) ? -1e9f : v;
            }

        // sigmoid store (coalesced float4 per row)
        #pragma unroll
        for (int i = 0; i < 4; i++) {
            float4 sg;
            sg.x = 1.0f / (1.0f + __expf(-s[i][0]));
            sg.y = 1.0f / (1.0f + __expf(-s[i][1]));
            sg.z = 1.0f / (1.0f + __expf(-s[i][2]));
            sg.w = 1.0f / (1.0f + __expf(-s[i][3]));
            *reinterpret_cast<float4*>(
                &sigbh[(size_t)(q0 + ty * 4 + i) * TT + kv0 + tx * 4]) = sg;
        }

        // online softmax: row max + exp + row sum (reduce across 16-lane group)
        float mnew[4], psum[4];
        #pragma unroll
        for (int i = 0; i < 4; i++) {
            float tm = fmaxf(fmaxf(s[i][0], s[i][1]), fmaxf(s[i][2], s[i][3]));
            #pragma unroll
            for (int off = 8; off; off >>= 1)
                tm = fmaxf(tm, __shfl_xor_sync(0xffffffffu, tm, off));
            mnew[i] = fmaxf(m_run[i], tm);
            float p0 = __expf(s[i][0] - mnew[i]);
            float p1 = __expf(s[i][1] - mnew[i]);
            float p2 = __expf(s[i][2] - mnew[i]);
            float p3 = __expf(s[i][3] - mnew[i]);
            s[i][0] = p0; s[i][1] = p1; s[i][2] = p2; s[i][3] = p3;
            float ps = p0 + p1 + p2 + p3;
            #pragma unroll
            for (int off = 8; off; off >>= 1)
                ps += __shfl_xor_sync(0xffffffffu, ps, off);
            psum[i] = ps;
        }

        __syncthreads();  // everyone done reading sKP as K
        #pragma unroll
        for (int i = 0; i < 4; i++) {
            *reinterpret_cast<float4*>(&sKP[ty * 4 + i][tx * 4]) =
                make_float4(s[i][0], s[i][1], s[i][2], s[i][3]);
        }
        __syncthreads();

        // rescale accumulators, update m,l
        #pragma unroll
        for (int i = 0; i < 4; i++) {
            float corr = __expf(m_run[i] - mnew[i]);
            l_run[i] = l_run[i] * corr + psum[i];
            m_run[i] = mnew[i];
            o[i][0] *= corr; o[i][1] *= corr; o[i][2] *= corr; o[i][3] *= corr;
        }

        // O += P @ V
        #pragma unroll
        for (int kk = 0; kk < 64; kk++) {
            float4 vv = *reinterpret_cast<const float4*>(&sV[kk][tx * 4]);
            float p0 = sKP[ty * 4 + 0][kk];
            float p1 = sKP[ty * 4 + 1][kk];
            float p2 = sKP[ty * 4 + 2][kk];
            float p3 = sKP[ty * 4 + 3][kk];
            o[0][0] += p0 * vv.x; o[0][1] += p0 * vv.y; o[0][2] += p0 * vv.z; o[0][3] += p0 * vv.w;
            o[1][0] += p1 * vv.x; o[1][1] += p1 * vv.y; o[1][2] += p1 * vv.z; o[1][3] += p1 * vv.w;
            o[2][0] += p2 * vv.x; o[2][1] += p2 * vv.y; o[2][2] += p2 * vv.z; o[2][3] += p2 * vv.w;
            o[3][0] += p3 * vv.x; o[3][1] += p3 * vv.y; o[3][2] += p3 * vv.z; o[3][3] += p3 * vv.w;
        }
    }

    // normalize + store to g_x
    #pragma unroll
    for (int i = 0; i < 4; i++) {
        float inv = 1.0f / l_run[i];
        float4 ov = make_float4(o[i][0] * inv, o[i][1] * inv,
                                o[i][2] * inv, o[i][3] * inv);
        *reinterpret_cast<float4*>(
            &g_x[((size_t)bh * TT + q0 + ty * 4 + i) * DKK + tx * 4]) = ov;
    }
}

// ---------------------------------------------------------------------------
// Output projection: out[m,n] = sum_k x[m,k] * Wo[n,k] + bo[n]
// x read from head-split g_x.
// ---------------------------------------------------------------------------
__global__ __launch_bounds__(256) void out_proj_kernel(
    const float* __restrict__ Wo, const float* __restrict__ bo,
    float* __restrict__ outp)
{
    __shared__ float sA[16][64];
    __shared__ float sB[16][64];

    const int tid = threadIdx.x;
    const int tx = tid & 15, ty = tid >> 4;
    const int m0 = blockIdx.y * 64;
    const int n0 = blockIdx.x * 64;
    const int lrow = tid >> 2;
    const int lk   = (tid & 3) * 4;

    float acc[4][4] = {};

    const int m = m0 + lrow;
    const int b_ = m >> 11, t_ = m & 2047;

    for (int k0 = 0; k0 < 512; k0 += 16) {
        const int k = k0 + lk;
        const int h_ = k >> 6, dk_ = k & 63;
        float4 av = *reinterpret_cast<const float4*>(
            &g_x[(((size_t)b_ * HH + h_) * TT + t_) * DKK + dk_]);
        float4 wv = *reinterpret_cast<const float4*>(&Wo[(n0 + lrow) * 512 + k]);
        __syncthreads();
        sA[lk + 0][lrow] = av.x; sA[lk + 1][lrow] = av.y;
        sA[lk + 2][lrow] = av.z; sA[lk + 3][lrow] = av.w;
        sB[lk + 0][lrow] = wv.x; sB[lk + 1][lrow] = wv.y;
        sB[lk + 2][lrow] = wv.z; sB[lk + 3][lrow] = wv.w;
        __syncthreads();
        #pragma unroll
        for (int kk = 0; kk < 16; kk++) {
            float4 a = *reinterpret_cast<const float4*>(&sA[kk][ty * 4]);
            float4 b = *reinterpret_cast<const float4*>(&sB[kk][tx * 4]);
            acc[0][0] += a.x * b.x; acc[0][1] += a.x * b.y; acc[0][2] += a.x * b.z; acc[0][3] += a.x * b.w;
            acc[1][0] += a.y * b.x; acc[1][1] += a.y * b.y; acc[1][2] += a.y * b.z; acc[1][3] += a.y * b.w;
            acc[2][0] += a.z * b.x; acc[2][1] += a.z * b.y; acc[2][2] += a.z * b.z; acc[2][3] += a.z * b.w;
            acc[3][0] += a.w * b.x; acc[3][1] += a.w * b.y; acc[3][2] += a.w * b.z; acc[3][3] += a.w * b.w;
        }
    }

    const int n = n0 + tx * 4;
    float4 bvv = *reinterpret_cast<const float4*>(&bo[n]);
    #pragma unroll
    for (int i = 0; i < 4; i++) {
        const int mm = m0 + ty * 4 + i;
        float4 ov;
        ov.x = acc[i][0] + bvv.x; ov.y = acc[i][1] + bvv.y;
        ov.z = acc[i][2] + bvv.z; ov.w = acc[i][3] + bvv.w;
        *reinterpret_cast<float4*>(&outp[(size_t)mm * 512 + n]) = ov;
    }
}

// ---------------------------------------------------------------------------
extern "C" void kernel_launch(void* const* d_in, const int* in_sizes, int n_in,
                              void* d_out, int out_size)
{
    const float* query = (const float*)d_in[0];
    const float* key   = (const float*)d_in[1];
    const float* value = (const float*)d_in[2];
    const int*   mask  = (const int*)d_in[3];
    const float* Wq = (const float*)d_in[4];
    const float* bq = (const float*)d_in[5];
    const float* Wk = (const float*)d_in[6];
    const float* bk = (const float*)d_in[7];
    const float* Wv = (const float*)d_in[8];
    const float* bv = (const float*)d_in[9];
    const float* Wo = (const float*)d_in[10];
    const float* bo = (const float*)d_in[11];

    float* out0 = (float*)d_out;                       // (B,T,D)
    float* sig  = out0 + (size_t)BB * TT * DD;         // (B,H,T,T)

    qkv_proj_kernel<<<dim3(8, 128, 3), 256>>>(query, key, value,
                                              Wq, bq, Wk, bk, Wv, bv);
    attn_kernel<<<dim3(TT / 64, BB * HH), 256>>>(mask, sig);
    out_proj_kernel<<<dim3(8, 128), 256>>>(Wo, bo, out0);
}

// round 4
// speedup vs baseline: 3.3088x; 3.3030x over previous
#include <cuda_runtime.h>
#include <cstdint>

#define BB 4
#define TT 2048
#define DD 512
#define HH 8
#define DKK 64

__device__ float g_q[BB*HH*TT*DKK];
__device__ float g_k[BB*HH*TT*DKK];
__device__ float g_v[BB*HH*TT*DKK];
__device__ float g_x[BB*HH*TT*DKK];

__device__ __forceinline__ float tf32r(float x){
    uint32_t r; asm("cvt.rna.tf32.f32 %0, %1;" : "=r"(r) : "f"(x));
    return __uint_as_float(r);
}
__device__ __forceinline__ float4 tf32r4(float4 v){
    return make_float4(tf32r(v.x), tf32r(v.y), tf32r(v.z), tf32r(v.w));
}

// D += A*B  (m16n8k8 tf32, row.col)
__device__ __forceinline__ void mma8(float* d, const uint32_t* a, const uint32_t* b){
    asm volatile(
      "mma.sync.aligned.m16n8k8.row.col.f32.tf32.tf32.f32 "
      "{%0,%1,%2,%3}, {%4,%5,%6,%7}, {%8,%9}, {%0,%1,%2,%3};"
      : "+f"(d[0]),"+f"(d[1]),"+f"(d[2]),"+f"(d[3])
      : "r"(a[0]),"r"(a[1]),"r"(a[2]),"r"(a[3]), "r"(b[0]),"r"(b[1]));
}

// =============================================================
// QKV projection: out[b,h,t,dk] = sum_k A[m,k]*W[n,k] + bias[n]
// CTA 128x128, warp grid 2(m) x 4(n), warp tile 64x32.
// =============================================================
__global__ __launch_bounds__(256, 2) void qkv_mma_kernel(
    const float* __restrict__ q_in, const float* __restrict__ k_in,
    const float* __restrict__ v_in,
    const float* __restrict__ Wq, const float* __restrict__ bq,
    const float* __restrict__ Wk, const float* __restrict__ bk,
    const float* __restrict__ Wv, const float* __restrict__ bv)
{
    const int which = blockIdx.z;
    const float* A    = which == 0 ? q_in : (which == 1 ? k_in : v_in);
    const float* W    = which == 0 ? Wq   : (which == 1 ? Wk   : Wv);
    const float* bias = which == 0 ? bq   : (which == 1 ? bk   : bv);
    float* outp       = which == 0 ? g_q  : (which == 1 ? g_k  : g_v);

    __shared__ float sA[128*36];
    __shared__ float sB[128*36];
    __shared__ float sBias[128];

    const int tid = threadIdx.x;
    const int lane = tid & 31, wid = tid >> 5;
    const int wm = wid & 1, wn = wid >> 1;
    const int m0 = blockIdx.y * 128, n0 = blockIdx.x * 128;

    if (tid < 32)
        *(float4*)&sBias[tid*4] = *(const float4*)(bias + n0 + tid*4);

    float acc[4][4][4] = {};

    for (int c = 0; c < 16; c++) {
        const int k0g = c * 32;
        __syncthreads();
        #pragma unroll
        for (int i = 0; i < 4; i++) {
            int idx = tid + i * 256;
            int row = idx >> 3, c4 = (idx & 7) * 4;
            float4 av = tf32r4(__ldg((const float4*)(A + (size_t)(m0+row)*512 + k0g + c4)));
            *(float4*)&sA[row*36 + c4] = av;
            float4 wv = tf32r4(__ldg((const float4*)(W + (size_t)(n0+row)*512 + k0g + c4)));
            *(float4*)&sB[row*36 + c4] = wv;
        }
        __syncthreads();
        #pragma unroll
        for (int ks = 0; ks < 4; ks++) {
            const int k0 = ks * 8;
            uint32_t af[4][4], bf[4][2];
            #pragma unroll
            for (int mt = 0; mt < 4; mt++) {
                const float* p = &sA[(wm*64 + mt*16 + (lane>>2))*36 + k0 + (lane&3)];
                af[mt][0] = __float_as_uint(p[0]);
                af[mt][1] = __float_as_uint(p[8*36]);
                af[mt][2] = __float_as_uint(p[4]);
                af[mt][3] = __float_as_uint(p[8*36+4]);
            }
            #pragma unroll
            for (int nt = 0; nt < 4; nt++) {
                const float* p = &sB[(wn*32 + nt*8 + (lane>>2))*36 + k0 + (lane&3)];
                bf[nt][0] = __float_as_uint(p[0]);
                bf[nt][1] = __float_as_uint(p[4]);
            }
            #pragma unroll
            for (int mt = 0; mt < 4; mt++)
                #pragma unroll
                for (int nt = 0; nt < 4; nt++)
                    mma8(acc[mt][nt], af[mt], bf[nt]);
        }
    }

    // epilogue: head-split store
    #pragma unroll
    for (int mt = 0; mt < 4; mt++) {
        const int m = m0 + wm*64 + mt*16 + (lane>>2);
        const int b0_ = m >> 11, t0_ = m & 2047;
        const int b1_ = (m+8) >> 11, t1_ = (m+8) & 2047;
        #pragma unroll
        for (int nt = 0; nt < 4; nt++) {
            const int nl = wn*32 + nt*8 + (lane&3)*2;
            const int n = n0 + nl;
            const int h_ = n >> 6, dk_ = n & 63;
            float bx = sBias[nl], by = sBias[nl+1];
            float* o0 = outp + (((size_t)b0_*HH + h_)*TT + t0_)*DKK + dk_;
            float* o1 = outp + (((size_t)b1_*HH + h_)*TT + t1_)*DKK + dk_;
            *(float2*)o0 = make_float2(acc[mt][nt][0] + bx, acc[mt][nt][1] + by);
            *(float2*)o1 = make_float2(acc[mt][nt][2] + bx, acc[mt][nt][3] + by);
        }
    }
}

// =============================================================
// Output projection: out[m,n] = sum_k x[m,k]*Wo[n,k] + bo[n]
// =============================================================
__global__ __launch_bounds__(256, 2) void oproj_mma_kernel(
    const float* __restrict__ Wo, const float* __restrict__ bo,
    float* __restrict__ outp)
{
    __shared__ float sA[128*36];
    __shared__ float sB[128*36];
    __shared__ float sBias[128];

    const int tid = threadIdx.x;
    const int lane = tid & 31, wid = tid >> 5;
    const int wm = wid & 1, wn = wid >> 1;
    const int m0 = blockIdx.y * 128, n0 = blockIdx.x * 128;

    if (tid < 32)
        *(float4*)&sBias[tid*4] = *(const float4*)(bo + n0 + tid*4);

    float acc[4][4][4] = {};

    for (int c = 0; c < 16; c++) {
        const int k0g = c * 32;
        const int h_ = k0g >> 6, dkb = k0g & 63;
        __syncthreads();
        #pragma unroll
        for (int i = 0; i < 4; i++) {
            int idx = tid + i * 256;
            int row = idx >> 3, c4 = (idx & 7) * 4;
            const int m = m0 + row;
            const int b_ = m >> 11, t_ = m & 2047;
            float4 av = tf32r4(__ldg((const float4*)(
                g_x + (((size_t)b_*HH + h_)*TT + t_)*DKK + dkb + c4)));
            *(float4*)&sA[row*36 + c4] = av;
            float4 wv = tf32r4(__ldg((const float4*)(Wo + (size_t)(n0+row)*512 + k0g + c4)));
            *(float4*)&sB[row*36 + c4] = wv;
        }
        __syncthreads();
        #pragma unroll
        for (int ks = 0; ks < 4; ks++) {
            const int k0 = ks * 8;
            uint32_t af[4][4], bf[4][2];
            #pragma unroll
            for (int mt = 0; mt < 4; mt++) {
                const float* p = &sA[(wm*64 + mt*16 + (lane>>2))*36 + k0 + (lane&3)];
                af[mt][0] = __float_as_uint(p[0]);
                af[mt][1] = __float_as_uint(p[8*36]);
                af[mt][2] = __float_as_uint(p[4]);
                af[mt][3] = __float_as_uint(p[8*36+4]);
            }
            #pragma unroll
            for (int nt = 0; nt < 4; nt++) {
                const float* p = &sB[(wn*32 + nt*8 + (lane>>2))*36 + k0 + (lane&3)];
                bf[nt][0] = __float_as_uint(p[0]);
                bf[nt][1] = __float_as_uint(p[4]);
            }
            #pragma unroll
            for (int mt = 0; mt < 4; mt++)
                #pragma unroll
                for (int nt = 0; nt < 4; nt++)
                    mma8(acc[mt][nt], af[mt], bf[nt]);
        }
    }

    #pragma unroll
    for (int mt = 0; mt < 4; mt++) {
        const int m = m0 + wm*64 + mt*16 + (lane>>2);
        #pragma unroll
        for (int nt = 0; nt < 4; nt++) {
            const int nl = wn*32 + nt*8 + (lane&3)*2;
            float bx = sBias[nl], by = sBias[nl+1];
            *(float2*)(outp + (size_t)m*512 + n0 + nl) =
                make_float2(acc[mt][nt][0] + bx, acc[mt][nt][1] + by);
            *(float2*)(outp + (size_t)(m+8)*512 + n0 + nl) =
                make_float2(acc[mt][nt][2] + bx, acc[mt][nt][3] + by);
        }
    }
}

// =============================================================
// Fused attention. CTA = (b,h, 128 q rows). Dynamic smem:
// sQ[128*68], sK[128*68], sV[128*72], sP[128*132], sM[128], sL[128]
// =============================================================
#define SQ_O 0
#define SK_O 8704
#define SV_O 17408
#define SP_O 26624
#define SM_O 43520
#define SL_O 43648
#define ATT_SMEM (43776*4)

__global__ __launch_bounds__(256, 1) void attn_mma_kernel(
    const int* __restrict__ mask, float* __restrict__ sig)
{
    extern __shared__ float sm[];
    float* sQ = sm + SQ_O;
    float* sK = sm + SK_O;
    float* sV = sm + SV_O;
    float* sP = sm + SP_O;
    float* sM = sm + SM_O;
    float* sL = sm + SL_O;

    const int tid = threadIdx.x;
    const int lane = tid & 31, wid = tid >> 5;
    const int wm = wid & 1,  wn = wid >> 1;   // S phase: 2x4
    const int wm2 = wid & 3, wn2 = wid >> 2;  // PV phase: 4x2
    const int bh = blockIdx.y;
    const int b_ = bh >> 3;
    const int q0 = blockIdx.x * 128;

    const float* Qg = g_q + (size_t)bh * TT * DKK;
    const float* Kg = g_k + (size_t)bh * TT * DKK;
    const float* Vg = g_v + (size_t)bh * TT * DKK;
    float* sigbh = sig + (size_t)bh * TT * TT;

    if (tid < 128) sL[tid] = 0.0f;

    // load Q tile
    #pragma unroll
    for (int i = 0; i < 8; i++) {
        int idx = tid + i * 256;
        int row = idx >> 4, c4 = (idx & 15) * 4;
        float4 v = tf32r4(__ldg((const float4*)(Qg + (size_t)(q0+row)*64 + c4)));
        *(float4*)&sQ[row*68 + c4] = v;
    }

    float o[2][4][4] = {};     // PV accumulators, persist across tiles
    float lsum[4][2] = {};     // row-sum partials (S-phase row mapping)

    for (int t = 0; t < 16; t++) {
        const int kv0 = t * 128;
        if (t > 0) __syncthreads();
        #pragma unroll
        for (int i = 0; i < 8; i++) {
            int idx = tid + i * 256;
            int row = idx >> 4, c4 = (idx & 15) * 4;
            float4 kv = tf32r4(__ldg((const float4*)(Kg + (size_t)(kv0+row)*64 + c4)));
            *(float4*)&sK[row*68 + c4] = kv;
            float4 vv = tf32r4(__ldg((const float4*)(Vg + (size_t)(kv0+row)*64 + c4)));
            *(float4*)&sV[row*72 + c4] = vv;
        }
        if (tid < 32) {
            int4 mm = __ldg((const int4*)(mask + b_*TT + kv0 + tid*4));
            sM[tid*4+0] = mm.x ? 0.0f : -1e9f;
            sM[tid*4+1] = mm.y ? 0.0f : -1e9f;
            sM[tid*4+2] = mm.z ? 0.0f : -1e9f;
            sM[tid*4+3] = mm.w ? 0.0f : -1e9f;
        }
        __syncthreads();

        // ---- S = Q @ K^T ----
        float s[4][4][4] = {};
        #pragma unroll
        for (int ks = 0; ks < 8; ks++) {
            const int k0 = ks * 8;
            uint32_t af[4][4], bf[4][2];
            #pragma unroll
            for (int mt = 0; mt < 4; mt++) {
                const float* p = &sQ[(wm*64 + mt*16 + (lane>>2))*68 + k0 + (lane&3)];
                af[mt][0] = __float_as_uint(p[0]);
                af[mt][1] = __float_as_uint(p[8*68]);
                af[mt][2] = __float_as_uint(p[4]);
                af[mt][3] = __float_as_uint(p[8*68+4]);
            }
            #pragma unroll
            for (int nt = 0; nt < 4; nt++) {
                const float* p = &sK[(wn*32 + nt*8 + (lane>>2))*68 + k0 + (lane&3)];
                bf[nt][0] = __float_as_uint(p[0]);
                bf[nt][1] = __float_as_uint(p[4]);
            }
            #pragma unroll
            for (int mt = 0; mt < 4; mt++)
                #pragma unroll
                for (int nt = 0; nt < 4; nt++)
                    mma8(s[mt][nt], af[mt], bf[nt]);
        }

        // ---- epilogue: sigmoid -> gmem, exp -> sP, row sums ----
        #pragma unroll
        for (int mt = 0; mt < 4; mt++) {
            const int r0 = wm*64 + mt*16 + (lane>>2);
            #pragma unroll
            for (int nt = 0; nt < 4; nt++) {
                const int cl = wn*32 + nt*8 + (lane&3)*2;
                const float m0_ = sM[cl], m1_ = sM[cl+1];
                float s0 = s[mt][nt][0]*0.125f + m0_;
                float s1 = s[mt][nt][1]*0.125f + m1_;
                float s2 = s[mt][nt][2]*0.125f + m0_;
                float s3 = s[mt][nt][3]*0.125f + m1_;
                float p0 = __expf(s0), p1 = __expf(s1);
                float p2 = __expf(s2), p3 = __expf(s3);
                *(float2*)(sigbh + (size_t)(q0+r0)*TT + kv0 + cl) =
                    make_float2(__fdividef(p0, 1.0f+p0), __fdividef(p1, 1.0f+p1));
                *(float2*)(sigbh + (size_t)(q0+r0+8)*TT + kv0 + cl) =
                    make_float2(__fdividef(p2, 1.0f+p2), __fdividef(p3, 1.0f+p3));
                lsum[mt][0] += p0 + p1;
                lsum[mt][1] += p2 + p3;
                *(float2*)&sP[r0*132 + cl]     = make_float2(tf32r(p0), tf32r(p1));
                *(float2*)&sP[(r0+8)*132 + cl] = make_float2(tf32r(p2), tf32r(p3));
            }
        }
        __syncthreads();

        // ---- O += P @ V ----
        #pragma unroll
        for (int ks = 0; ks < 16; ks++) {
            const int k0 = ks * 8;
            uint32_t af[2][4], bf[4][2];
            #pragma unroll
            for (int mt = 0; mt < 2; mt++) {
                const float* p = &sP[(wm2*32 + mt*16 + (lane>>2))*132 + k0 + (lane&3)];
                af[mt][0] = __float_as_uint(p[0]);
                af[mt][1] = __float_as_uint(p[8*132]);
                af[mt][2] = __float_as_uint(p[4]);
                af[mt][3] = __float_as_uint(p[8*132+4]);
            }
            #pragma unroll
            for (int nt = 0; nt < 4; nt++) {
                const float* p = &sV[(k0 + (lane&3))*72 + wn2*32 + nt*8 + (lane>>2)];
                bf[nt][0] = __float_as_uint(p[0]);
                bf[nt][1] = __float_as_uint(p[4*72]);
            }
            #pragma unroll
            for (int mt = 0; mt < 2; mt++)
                #pragma unroll
                for (int nt = 0; nt < 4; nt++)
                    mma8(o[mt][nt], af[mt], bf[nt]);
        }
    }

    // ---- reduce row sums ----
    #pragma unroll
    for (int mt = 0; mt < 4; mt++)
        #pragma unroll
        for (int h = 0; h < 2; h++) {
            float v = lsum[mt][h];
            v += __shfl_xor_sync(0xffffffffu, v, 1);
            v += __shfl_xor_sync(0xffffffffu, v, 2);
            if ((lane & 3) == 0)
                atomicAdd(&sL[wm*64 + mt*16 + (lane>>2) + h*8], v);
        }
    __syncthreads();

    // ---- normalize + store O ----
    #pragma unroll
    for (int mt = 0; mt < 2; mt++) {
        const int r = wm2*32 + mt*16 + (lane>>2);
        const float li0 = 1.0f / sL[r];
        const float li1 = 1.0f / sL[r+8];
        #pragma unroll
        for (int nt = 0; nt < 4; nt++) {
            const int cc = wn2*32 + nt*8 + (lane&3)*2;
            *(float2*)(g_x + ((size_t)bh*TT + q0 + r)*DKK + cc) =
                make_float2(o[mt][nt][0]*li0, o[mt][nt][1]*li0);
            *(float2*)(g_x + ((size_t)bh*TT + q0 + r + 8)*DKK + cc) =
                make_float2(o[mt][nt][2]*li1, o[mt][nt][3]*li1);
        }
    }
}

// -------------------------------------------------------------
extern "C" void kernel_launch(void* const* d_in, const int* in_sizes, int n_in,
                              void* d_out, int out_size)
{
    const float* query = (const float*)d_in[0];
    const float* key   = (const float*)d_in[1];
    const float* value = (const float*)d_in[2];
    const int*   mask  = (const int*)d_in[3];
    const float* Wq = (const float*)d_in[4];
    const float* bq = (const float*)d_in[5];
    const float* Wk = (const float*)d_in[6];
    const float* bk = (const float*)d_in[7];
    const float* Wv = (const float*)d_in[8];
    const float* bv = (const float*)d_in[9];
    const float* Wo = (const float*)d_in[10];
    const float* bo = (const float*)d_in[11];

    float* out0 = (float*)d_out;                 // (B,T,D)
    float* sig  = out0 + (size_t)BB * TT * DD;   // (B,H,T,T)

    static bool configured = false;
    if (!configured) {
        cudaFuncSetAttribute(attn_mma_kernel,
            cudaFuncAttributeMaxDynamicSharedMemorySize, ATT_SMEM);
        configured = true;
    }

    qkv_mma_kernel<<<dim3(4, 64, 3), 256>>>(query, key, value,
                                            Wq, bq, Wk, bk, Wv, bv);
    attn_mma_kernel<<<dim3(16, 32), 256, ATT_SMEM>>>(mask, sig);
    oproj_mma_kernel<<<dim3(4, 64), 256>>>(Wo, bo, out0);
}

// round 5
// speedup vs baseline: 5.1025x; 1.5421x over previous
#include <cuda_runtime.h>
#include <cuda_fp16.h>
#include <cstdint>

#define BB 4
#define TT 2048
#define DD 512
#define HH 8
#define DKK 64

// fp16 scratch. q/k/x: [b,h,t,dk].  v: TRANSPOSED [b,h,dk,t].
__device__ __half g_qh[BB*HH*TT*DKK];
__device__ __half g_kh[BB*HH*TT*DKK];
__device__ __half g_vh[BB*HH*TT*DKK];
__device__ __half g_xh[BB*HH*TT*DKK];

// D += A*B  (m16n8k16 fp16 -> fp32)
__device__ __forceinline__ void mma16(float* d, const uint32_t* a, const uint32_t* b){
    asm volatile(
      "mma.sync.aligned.m16n8k16.row.col.f32.f16.f16.f32 "
      "{%0,%1,%2,%3}, {%4,%5,%6,%7}, {%8,%9}, {%0,%1,%2,%3};"
      : "+f"(d[0]),"+f"(d[1]),"+f"(d[2]),"+f"(d[3])
      : "r"(a[0]),"r"(a[1]),"r"(a[2]),"r"(a[3]), "r"(b[0]),"r"(b[1]));
}
__device__ __forceinline__ uint2 f4h(float4 v){
    __half2 lo = __floats2half2_rn(v.x, v.y);
    __half2 hi = __floats2half2_rn(v.z, v.w);
    return make_uint2(*(uint32_t*)&lo, *(uint32_t*)&hi);
}

// =============================================================
// QKV projection (fp16 MMA): CTA 128x128, warps 2(m)x4(n), chunk K=64.
// =============================================================
__global__ __launch_bounds__(256, 2) void qkv_mma_kernel(
    const float* __restrict__ q_in, const float* __restrict__ k_in,
    const float* __restrict__ v_in,
    const float* __restrict__ Wq, const float* __restrict__ bq,
    const float* __restrict__ Wk, const float* __restrict__ bk,
    const float* __restrict__ Wv, const float* __restrict__ bv)
{
    const int which = blockIdx.z;
    const float* A    = which == 0 ? q_in : (which == 1 ? k_in : v_in);
    const float* W    = which == 0 ? Wq   : (which == 1 ? Wk   : Wv);
    const float* bias = which == 0 ? bq   : (which == 1 ? bk   : bv);
    __half* outp      = which == 0 ? g_qh : (which == 1 ? g_kh : g_vh);

    __shared__ __half sA[128*72];
    __shared__ __half sB[128*72];
    __shared__ float  sBias[128];

    const int tid = threadIdx.x;
    const int lane = tid & 31, wid = tid >> 5;
    const int wm = wid & 1, wn = wid >> 1;
    const int m0 = blockIdx.y * 128, n0 = blockIdx.x * 128;

    if (tid < 32)
        *(float4*)&sBias[tid*4] = *(const float4*)(bias + n0 + tid*4);

    float acc[4][4][4] = {};

    for (int c = 0; c < 8; c++) {
        const int k0g = c * 64;
        __syncthreads();
        #pragma unroll
        for (int i = 0; i < 8; i++) {
            int u = tid + i * 256;
            int row = u >> 4, c4 = (u & 15) * 4;
            float4 av = __ldg((const float4*)(A + (size_t)(m0+row)*512 + k0g + c4));
            *(uint2*)&sA[row*72 + c4] = f4h(av);
            float4 wv = __ldg((const float4*)(W + (size_t)(n0+row)*512 + k0g + c4));
            *(uint2*)&sB[row*72 + c4] = f4h(wv);
        }
        __syncthreads();
        #pragma unroll
        for (int ks = 0; ks < 4; ks++) {
            const int k0 = ks * 16 + (lane & 3) * 2;
            uint32_t af[4][4], bf[4][2];
            #pragma unroll
            for (int mt = 0; mt < 4; mt++) {
                const __half* p = &sA[(wm*64 + mt*16 + (lane>>2))*72 + k0];
                af[mt][0] = *(const uint32_t*)p;
                af[mt][1] = *(const uint32_t*)(p + 8*72);
                af[mt][2] = *(const uint32_t*)(p + 8);
                af[mt][3] = *(const uint32_t*)(p + 8*72 + 8);
            }
            #pragma unroll
            for (int nt = 0; nt < 4; nt++) {
                const __half* p = &sB[(wn*32 + nt*8 + (lane>>2))*72 + k0];
                bf[nt][0] = *(const uint32_t*)p;
                bf[nt][1] = *(const uint32_t*)(p + 8);
            }
            #pragma unroll
            for (int mt = 0; mt < 4; mt++)
                #pragma unroll
                for (int nt = 0; nt < 4; nt++)
                    mma16(acc[mt][nt], af[mt], bf[nt]);
        }
    }

    #pragma unroll
    for (int mt = 0; mt < 4; mt++) {
        const int m = m0 + wm*64 + mt*16 + (lane>>2);
        const int b0_ = m >> 11, t0_ = m & 2047;
        const int b1_ = (m+8) >> 11, t1_ = (m+8) & 2047;
        #pragma unroll
        for (int nt = 0; nt < 4; nt++) {
            const int nl = wn*32 + nt*8 + (lane&3)*2;
            const int n = n0 + nl;
            const int h_ = n >> 6, dk_ = n & 63;
            float bx = sBias[nl], by = sBias[nl+1];
            float v0 = acc[mt][nt][0] + bx, v1 = acc[mt][nt][1] + by;
            float v2 = acc[mt][nt][2] + bx, v3 = acc[mt][nt][3] + by;
            if (which == 2) {
                // transposed store: g_vh[(b,h,dk)][t]
                __half* base = outp + ((size_t)(b0_*HH + h_)*DKK + dk_)*TT;
                base[t0_]        = __float2half_rn(v0);
                base[TT + t0_]   = __float2half_rn(v1);
                __half* base1 = outp + ((size_t)(b1_*HH + h_)*DKK + dk_)*TT;
                base1[t1_]       = __float2half_rn(v2);
                base1[TT + t1_]  = __float2half_rn(v3);
            } else {
                __half2 h01 = __floats2half2_rn(v0, v1);
                __half2 h23 = __floats2half2_rn(v2, v3);
                *(__half2*)(outp + (((size_t)b0_*HH + h_)*TT + t0_)*DKK + dk_) = h01;
                *(__half2*)(outp + (((size_t)b1_*HH + h_)*TT + t1_)*DKK + dk_) = h23;
            }
        }
    }
}

// =============================================================
// Output projection: reads g_xh (fp16), Wo fp32->fp16, out fp32+bias
// =============================================================
__global__ __launch_bounds__(256, 2) void oproj_mma_kernel(
    const float* __restrict__ Wo, const float* __restrict__ bo,
    float* __restrict__ outp)
{
    __shared__ __half sA[128*72];
    __shared__ __half sB[128*72];
    __shared__ float  sBias[128];

    const int tid = threadIdx.x;
    const int lane = tid & 31, wid = tid >> 5;
    const int wm = wid & 1, wn = wid >> 1;
    const int m0 = blockIdx.y * 128, n0 = blockIdx.x * 128;

    if (tid < 32)
        *(float4*)&sBias[tid*4] = *(const float4*)(bo + n0 + tid*4);

    float acc[4][4][4] = {};

    for (int c = 0; c < 8; c++) {          // chunk c == head c
        const int k0g = c * 64;
        __syncthreads();
        #pragma unroll
        for (int i = 0; i < 4; i++) {      // A: fp16 direct, uint4 = 8 halves
            int u = tid + i * 256;
            int row = u >> 3, c8 = (u & 7) * 8;
            const int m = m0 + row;
            const int b_ = m >> 11, t_ = m & 2047;
            uint4 av = __ldg((const uint4*)(g_xh + (((size_t)b_*HH + c)*TT + t_)*DKK + c8));
            *(uint4*)&sA[row*72 + c8] = av;
        }
        #pragma unroll
        for (int i = 0; i < 8; i++) {      // B: fp32 -> fp16
            int u = tid + i * 256;
            int row = u >> 4, c4 = (u & 15) * 4;
            float4 wv = __ldg((const float4*)(Wo + (size_t)(n0+row)*512 + k0g + c4));
            *(uint2*)&sB[row*72 + c4] = f4h(wv);
        }
        __syncthreads();
        #pragma unroll
        for (int ks = 0; ks < 4; ks++) {
            const int k0 = ks * 16 + (lane & 3) * 2;
            uint32_t af[4][4], bf[4][2];
            #pragma unroll
            for (int mt = 0; mt < 4; mt++) {
                const __half* p = &sA[(wm*64 + mt*16 + (lane>>2))*72 + k0];
                af[mt][0] = *(const uint32_t*)p;
                af[mt][1] = *(const uint32_t*)(p + 8*72);
                af[mt][2] = *(const uint32_t*)(p + 8);
                af[mt][3] = *(const uint32_t*)(p + 8*72 + 8);
            }
            #pragma unroll
            for (int nt = 0; nt < 4; nt++) {
                const __half* p = &sB[(wn*32 + nt*8 + (lane>>2))*72 + k0];
                bf[nt][0] = *(const uint32_t*)p;
                bf[nt][1] = *(const uint32_t*)(p + 8);
            }
            #pragma unroll
            for (int mt = 0; mt < 4; mt++)
                #pragma unroll
                for (int nt = 0; nt < 4; nt++)
                    mma16(acc[mt][nt], af[mt], bf[nt]);
        }
    }

    #pragma unroll
    for (int mt = 0; mt < 4; mt++) {
        const int m = m0 + wm*64 + mt*16 + (lane>>2);
        #pragma unroll
        for (int nt = 0; nt < 4; nt++) {
            const int nl = wn*32 + nt*8 + (lane&3)*2;
            float bx = sBias[nl], by = sBias[nl+1];
            *(float2*)(outp + (size_t)m*512 + n0 + nl) =
                make_float2(acc[mt][nt][0] + bx, acc[mt][nt][1] + by);
            *(float2*)(outp + (size_t)(m+8)*512 + n0 + nl) =
                make_float2(acc[mt][nt][2] + bx, acc[mt][nt][3] + by);
        }
    }
}

// =============================================================
// Fused attention, fp16. CTA = (b,h, 128 q rows), 2 CTAs/SM.
// smem bytes: sQ@0 (128x72 h =18432), sK@18432 (18432),
// sVt@36864 (64x136 h =17408), sP@54272 (128x136 h =34816),
// sM@89088 (512), sL@89600 (512) -> 90112 total
// =============================================================
#define SQ_O 0
#define SK_O 18432
#define SVT_O 36864
#define SP_O 54272
#define SM_O 89088
#define SL_O 89600
#define ATT_SMEM 90112

__global__ __launch_bounds__(256, 2) void attn_mma_kernel(
    const int* __restrict__ mask, float* __restrict__ sig)
{
    extern __shared__ char smn[];
    __half* sQ  = (__half*)(smn + SQ_O);
    __half* sK  = (__half*)(smn + SK_O);
    __half* sVt = (__half*)(smn + SVT_O);
    __half* sP  = (__half*)(smn + SP_O);
    float*  sM  = (float*)(smn + SM_O);
    float*  sL  = (float*)(smn + SL_O);

    const int tid = threadIdx.x;
    const int lane = tid & 31, wid = tid >> 5;
    const int wm = wid & 1,  wn = wid >> 1;   // S phase: 2x4
    const int wm2 = wid & 3, wn2 = wid >> 2;  // PV phase: 4x2
    const int bh = blockIdx.y;
    const int b_ = bh >> 3;
    const int q0 = blockIdx.x * 128;

    const __half* Qg = g_qh + (size_t)bh * TT * DKK;
    const __half* Kg = g_kh + (size_t)bh * TT * DKK;
    const __half* Vg = g_vh + (size_t)bh * DKK * TT;   // transposed [dk][t]
    float* sigbh = sig + (size_t)bh * TT * TT;

    if (tid < 128) sL[tid] = 0.0f;

    // load Q tile (fp16 direct)
    #pragma unroll
    for (int i = 0; i < 4; i++) {
        int u = tid + i * 256;
        int row = u >> 3, c8 = (u & 7) * 8;
        uint4 v = __ldg((const uint4*)(Qg + (size_t)(q0+row)*DKK + c8));
        *(uint4*)&sQ[row*72 + c8] = v;
    }

    float o[2][4][4] = {};
    float lsum[4][2] = {};

    for (int t = 0; t < 16; t++) {
        const int kv0 = t * 128;
        if (t > 0) __syncthreads();
        #pragma unroll
        for (int i = 0; i < 4; i++) {
            int u = tid + i * 256;
            int krow = u >> 3, kc8 = (u & 7) * 8;
            uint4 kv = __ldg((const uint4*)(Kg + (size_t)(kv0+krow)*DKK + kc8));
            *(uint4*)&sK[krow*72 + kc8] = kv;
            int dk = u >> 4, vc8 = (u & 15) * 8;
            uint4 vv = __ldg((const uint4*)(Vg + (size_t)dk*TT + kv0 + vc8));
            *(uint4*)&sVt[dk*136 + vc8] = vv;
        }
        if (tid < 32) {
            int4 mm = __ldg((const int4*)(mask + b_*TT + kv0 + tid*4));
            sM[tid*4+0] = mm.x ? 0.0f : -1e9f;
            sM[tid*4+1] = mm.y ? 0.0f : -1e9f;
            sM[tid*4+2] = mm.z ? 0.0f : -1e9f;
            sM[tid*4+3] = mm.w ? 0.0f : -1e9f;
        }
        __syncthreads();

        // S = Q @ K^T, processed in two column halves (reg pressure)
        #pragma unroll
        for (int hn = 0; hn < 2; hn++) {
            float s[4][2][4] = {};
            #pragma unroll
            for (int ks = 0; ks < 4; ks++) {
                const int k0 = ks * 16 + (lane & 3) * 2;
                uint32_t af[4][4], bf[2][2];
                #pragma unroll
                for (int mt = 0; mt < 4; mt++) {
                    const __half* p = &sQ[(wm*64 + mt*16 + (lane>>2))*72 + k0];
                    af[mt][0] = *(const uint32_t*)p;
                    af[mt][1] = *(const uint32_t*)(p + 8*72);
                    af[mt][2] = *(const uint32_t*)(p + 8);
                    af[mt][3] = *(const uint32_t*)(p + 8*72 + 8);
                }
                #pragma unroll
                for (int j = 0; j < 2; j++) {
                    const int nt = hn*2 + j;
                    const __half* p = &sK[(wn*32 + nt*8 + (lane>>2))*72 + k0];
                    bf[j][0] = *(const uint32_t*)p;
                    bf[j][1] = *(const uint32_t*)(p + 8);
                }
                #pragma unroll
                for (int mt = 0; mt < 4; mt++)
                    #pragma unroll
                    for (int j = 0; j < 2; j++)
                        mma16(s[mt][j], af[mt], bf[j]);
            }
            // epilogue for this half
            #pragma unroll
            for (int mt = 0; mt < 4; mt++) {
                const int r0 = wm*64 + mt*16 + (lane>>2);
                #pragma unroll
                for (int j = 0; j < 2; j++) {
                    const int cl = wn*32 + (hn*2+j)*8 + (lane&3)*2;
                    const float m0_ = sM[cl], m1_ = sM[cl+1];
                    float s0 = s[mt][j][0]*0.125f + m0_;
                    float s1 = s[mt][j][1]*0.125f + m1_;
                    float s2 = s[mt][j][2]*0.125f + m0_;
                    float s3 = s[mt][j][3]*0.125f + m1_;
                    float p0 = __expf(s0), p1 = __expf(s1);
                    float p2 = __expf(s2), p3 = __expf(s3);
                    *(float2*)(sigbh + (size_t)(q0+r0)*TT + kv0 + cl) =
                        make_float2(__fdividef(p0, 1.0f+p0), __fdividef(p1, 1.0f+p1));
                    *(float2*)(sigbh + (size_t)(q0+r0+8)*TT + kv0 + cl) =
                        make_float2(__fdividef(p2, 1.0f+p2), __fdividef(p3, 1.0f+p3));
                    lsum[mt][0] += p0 + p1;
                    lsum[mt][1] += p2 + p3;
                    *(__half2*)&sP[r0*136 + cl]     = __floats2half2_rn(p0, p1);
                    *(__half2*)&sP[(r0+8)*136 + cl] = __floats2half2_rn(p2, p3);
                }
            }
        }
        __syncthreads();

        // O += P @ V   (A = sP row-major, B = sVt[dk][kv])
        #pragma unroll
        for (int ks = 0; ks < 8; ks++) {
            const int k0 = ks * 16 + (lane & 3) * 2;
            uint32_t af[2][4], bf[4][2];
            #pragma unroll
            for (int mt = 0; mt < 2; mt++) {
                const __half* p = &sP[(wm2*32 + mt*16 + (lane>>2))*136 + k0];
                af[mt][0] = *(const uint32_t*)p;
                af[mt][1] = *(const uint32_t*)(p + 8*136);
                af[mt][2] = *(const uint32_t*)(p + 8);
                af[mt][3] = *(const uint32_t*)(p + 8*136 + 8);
            }
            #pragma unroll
            for (int nt = 0; nt < 4; nt++) {
                const __half* p = &sVt[(wn2*32 + nt*8 + (lane>>2))*136 + k0];
                bf[nt][0] = *(const uint32_t*)p;
                bf[nt][1] = *(const uint32_t*)(p + 8);
            }
            #pragma unroll
            for (int mt = 0; mt < 2; mt++)
                #pragma unroll
                for (int nt = 0; nt < 4; nt++)
                    mma16(o[mt][nt], af[mt], bf[nt]);
        }
    }

    // reduce row sums
    #pragma unroll
    for (int mt = 0; mt < 4; mt++)
        #pragma unroll
        for (int h = 0; h < 2; h++) {
            float v = lsum[mt][h];
            v += __shfl_xor_sync(0xffffffffu, v, 1);
            v += __shfl_xor_sync(0xffffffffu, v, 2);
            if ((lane & 3) == 0)
                atomicAdd(&sL[wm*64 + mt*16 + (lane>>2) + h*8], v);
        }
    __syncthreads();

    // normalize + store X (fp16)
    #pragma unroll
    for (int mt = 0; mt < 2; mt++) {
        const int r = wm2*32 + mt*16 + (lane>>2);
        const float li0 = 1.0f / sL[r];
        const float li1 = 1.0f / sL[r+8];
        #pragma unroll
        for (int nt = 0; nt < 4; nt++) {
            const int cc = wn2*32 + nt*8 + (lane&3)*2;
            *(__half2*)(g_xh + ((size_t)bh*TT + q0 + r)*DKK + cc) =
                __floats2half2_rn(o[mt][nt][0]*li0, o[mt][nt][1]*li0);
            *(__half2*)(g_xh + ((size_t)bh*TT + q0 + r + 8)*DKK + cc) =
                __floats2half2_rn(o[mt][nt][2]*li1, o[mt][nt][3]*li1);
        }
    }
}

// -------------------------------------------------------------
extern "C" void kernel_launch(void* const* d_in, const int* in_sizes, int n_in,
                              void* d_out, int out_size)
{
    const float* query = (const float*)d_in[0];
    const float* key   = (const float*)d_in[1];
    const float* value = (const float*)d_in[2];
    const int*   mask  = (const int*)d_in[3];
    const float* Wq = (const float*)d_in[4];
    const float* bq = (const float*)d_in[5];
    const float* Wk = (const float*)d_in[6];
    const float* bk = (const float*)d_in[7];
    const float* Wv = (const float*)d_in[8];
    const float* bv = (const float*)d_in[9];
    const float* Wo = (const float*)d_in[10];
    const float* bo = (const float*)d_in[11];

    float* out0 = (float*)d_out;                 // (B,T,D)
    float* sig  = out0 + (size_t)BB * TT * DD;   // (B,H,T,T)

    static bool configured = false;
    if (!configured) {
        cudaFuncSetAttribute(attn_mma_kernel,
            cudaFuncAttributeMaxDynamicSharedMemorySize, ATT_SMEM);
        configured = true;
    }

    qkv_mma_kernel<<<dim3(4, 64, 3), 256>>>(query, key, value,
                                            Wq, bq, Wk, bk, Wv, bv);
    attn_mma_kernel<<<dim3(16, 32), 256, ATT_SMEM>>>(mask, sig);
    oproj_mma_kernel<<<dim3(4, 64), 256>>>(Wo, bo, out0);
}

// round 6
// speedup vs baseline: 5.5273x; 1.0833x over previous
#include <cuda_runtime.h>
#include <cuda_fp16.h>
#include <cstdint>

#define BB 4
#define TT 2048
#define DD 512
#define HH 8
#define DKK 64

// fp16 scratch. q/k/x: [b,h,t,dk].  v: TRANSPOSED [b,h,dk,t].
__device__ __half g_qh[BB*HH*TT*DKK];
__device__ __half g_kh[BB*HH*TT*DKK];
__device__ __half g_vh[BB*HH*TT*DKK];
__device__ __half g_xh[BB*HH*TT*DKK];
// fp16 copies of inputs/weights
__device__ __half g_qi[BB*TT*DD];
__device__ __half g_ki[BB*TT*DD];
__device__ __half g_vi[BB*TT*DD];
__device__ __half g_wq[DD*DD];
__device__ __half g_wk[DD*DD];
__device__ __half g_wv[DD*DD];
__device__ __half g_wo[DD*DD];

__device__ __forceinline__ void mma16(float* d, const uint32_t* a, const uint32_t* b){
    asm volatile(
      "mma.sync.aligned.m16n8k16.row.col.f32.f16.f16.f32 "
      "{%0,%1,%2,%3}, {%4,%5,%6,%7}, {%8,%9}, {%0,%1,%2,%3};"
      : "+f"(d[0]),"+f"(d[1]),"+f"(d[2]),"+f"(d[3])
      : "r"(a[0]),"r"(a[1]),"r"(a[2]),"r"(a[3]), "r"(b[0]),"r"(b[1]));
}
__device__ __forceinline__ uint2 f4h(float4 v){
    __half2 lo = __floats2half2_rn(v.x, v.y);
    __half2 hi = __floats2half2_rn(v.z, v.w);
    return make_uint2(*(uint32_t*)&lo, *(uint32_t*)&hi);
}
__device__ __forceinline__ uint32_t smem_u32(const void* p){
    uint32_t a;
    asm("{ .reg .u64 t; cvta.to.shared.u64 t, %1; cvt.u32.u64 %0, t; }"
        : "=r"(a) : "l"(p));
    return a;
}
__device__ __forceinline__ void cp16(uint32_t s, const void* g){
    asm volatile("cp.async.cg.shared.global [%0], [%1], 16;" :: "r"(s), "l"(g) : "memory");
}
__device__ __forceinline__ void cpcommit(){
    asm volatile("cp.async.commit_group;" ::: "memory");
}
template<int N> __device__ __forceinline__ void cpwait(){
    asm volatile("cp.async.wait_group %0;" :: "n"(N) : "memory");
}

// =============================================================
// Convert fp32 inputs + weights to fp16 scratch
// =============================================================
#define IN4 1048576
#define W4  65536
__global__ __launch_bounds__(256) void cvt_kernel(
    const float* __restrict__ q, const float* __restrict__ k,
    const float* __restrict__ v,
    const float* __restrict__ Wq, const float* __restrict__ Wk,
    const float* __restrict__ Wv, const float* __restrict__ Wo)
{
    int i = blockIdx.x * 256 + threadIdx.x;
    const float* s; __half* d; int off;
    if (i < 3*IN4) {
        int w = i / IN4; off = i - w*IN4;
        s = w==0 ? q : (w==1 ? k : v);
        d = w==0 ? g_qi : (w==1 ? g_ki : g_vi);
    } else {
        int j = i - 3*IN4;
        int w = j / W4; off = j - w*W4;
        s = w==0 ? Wq : (w==1 ? Wk : (w==2 ? Wv : Wo));
        d = w==0 ? g_wq : (w==1 ? g_wk : (w==2 ? g_wv : g_wo));
    }
    float4 vv = __ldg((const float4*)s + off);
    *(uint2*)(d + (size_t)off*4) = f4h(vv);
}

// =============================================================
// QKV projection, fp16 + cp.async 2-stage. CTA 128x128, warps 2x4.
// smem: sA0@0 sB0@18432 sA1@36864 sB1@55296  bias@73728  (74240 B)
// =============================================================
#define PJ_SMEM 74240

__global__ __launch_bounds__(256, 2) void qkv_mma_kernel(
    const float* __restrict__ bq, const float* __restrict__ bk,
    const float* __restrict__ bv)
{
    extern __shared__ char smn[];
    const int which = blockIdx.z;
    const __half* A  = which == 0 ? g_qi : (which == 1 ? g_ki : g_vi);
    const __half* W  = which == 0 ? g_wq : (which == 1 ? g_wk : g_wv);
    const float* bias= which == 0 ? bq   : (which == 1 ? bk   : bv);
    __half* outp     = which == 0 ? g_qh : (which == 1 ? g_kh : g_vh);

    float* sBias = (float*)(smn + 73728);
    const uint32_t sb = smem_u32(smn);

    const int tid = threadIdx.x;
    const int lane = tid & 31, wid = tid >> 5;
    const int wm = wid & 1, wn = wid >> 1;
    const int m0 = blockIdx.y * 128, n0 = blockIdx.x * 128;

    if (tid < 32)
        *(float4*)&sBias[tid*4] = *(const float4*)(bias + n0 + tid*4);

    const int lrow = tid >> 3, lc8 = (tid & 7) * 8;

    // issue chunk cc into stage s
    auto issue = [&](int cc, int s){
        #pragma unroll
        for (int i = 0; i < 4; i++) {
            int row = lrow + i * 32;
            uint32_t so = sb + s*36864 + row*144 + lc8*2;
            cp16(so, A + (size_t)(m0+row)*512 + cc*64 + lc8);
            cp16(so + 18432, W + (size_t)(n0+row)*512 + cc*64 + lc8);
        }
        cpcommit();
    };

    issue(0, 0);
    issue(1, 1);

    float acc[4][4][4] = {};

    for (int c = 0; c < 8; c++) {
        if (c < 7) cpwait<1>(); else cpwait<0>();
        __syncthreads();
        const __half* sA = (const __half*)(smn + (c & 1) * 36864);
        const __half* sB = sA + 9216;
        #pragma unroll
        for (int ks = 0; ks < 4; ks++) {
            const int k0 = ks * 16 + (lane & 3) * 2;
            uint32_t af[4][4], bf[4][2];
            #pragma unroll
            for (int mt = 0; mt < 4; mt++) {
                const __half* p = &sA[(wm*64 + mt*16 + (lane>>2))*72 + k0];
                af[mt][0] = *(const uint32_t*)p;
                af[mt][1] = *(const uint32_t*)(p + 8*72);
                af[mt][2] = *(const uint32_t*)(p + 8);
                af[mt][3] = *(const uint32_t*)(p + 8*72 + 8);
            }
            #pragma unroll
            for (int nt = 0; nt < 4; nt++) {
                const __half* p = &sB[(wn*32 + nt*8 + (lane>>2))*72 + k0];
                bf[nt][0] = *(const uint32_t*)p;
                bf[nt][1] = *(const uint32_t*)(p + 8);
            }
            #pragma unroll
            for (int mt = 0; mt < 4; mt++)
                #pragma unroll
                for (int nt = 0; nt < 4; nt++)
                    mma16(acc[mt][nt], af[mt], bf[nt]);
        }
        __syncthreads();
        if (c + 2 < 8) issue(c + 2, c & 1);
    }

    #pragma unroll
    for (int mt = 0; mt < 4; mt++) {
        const int m = m0 + wm*64 + mt*16 + (lane>>2);
        const int b0_ = m >> 11, t0_ = m & 2047;
        const int b1_ = (m+8) >> 11, t1_ = (m+8) & 2047;
        #pragma unroll
        for (int nt = 0; nt < 4; nt++) {
            const int nl = wn*32 + nt*8 + (lane&3)*2;
            const int n = n0 + nl;
            const int h_ = n >> 6, dk_ = n & 63;
            float bx = sBias[nl], by = sBias[nl+1];
            float v0 = acc[mt][nt][0] + bx, v1 = acc[mt][nt][1] + by;
            float v2 = acc[mt][nt][2] + bx, v3 = acc[mt][nt][3] + by;
            if (which == 2) {
                __half* base = outp + ((size_t)(b0_*HH + h_)*DKK + dk_)*TT;
                base[t0_]       = __float2half_rn(v0);
                base[TT + t0_]  = __float2half_rn(v1);
                __half* base1 = outp + ((size_t)(b1_*HH + h_)*DKK + dk_)*TT;
                base1[t1_]      = __float2half_rn(v2);
                base1[TT + t1_] = __float2half_rn(v3);
            } else {
                *(__half2*)(outp + (((size_t)b0_*HH + h_)*TT + t0_)*DKK + dk_) =
                    __floats2half2_rn(v0, v1);
                *(__half2*)(outp + (((size_t)b1_*HH + h_)*TT + t1_)*DKK + dk_) =
                    __floats2half2_rn(v2, v3);
            }
        }
    }
}

// =============================================================
// Output projection: A = g_xh (head-split fp16), B = g_wo fp16
// =============================================================
__global__ __launch_bounds__(256, 2) void oproj_mma_kernel(
    const float* __restrict__ bo, float* __restrict__ outp)
{
    extern __shared__ char smn[];
    float* sBias = (float*)(smn + 73728);
    const uint32_t sb = smem_u32(smn);

    const int tid = threadIdx.x;
    const int lane = tid & 31, wid = tid >> 5;
    const int wm = wid & 1, wn = wid >> 1;
    const int m0 = blockIdx.y * 128, n0 = blockIdx.x * 128;

    if (tid < 32)
        *(float4*)&sBias[tid*4] = *(const float4*)(bo + n0 + tid*4);

    const int lrow = tid >> 3, lc8 = (tid & 7) * 8;

    auto issue = [&](int cc, int s){
        #pragma unroll
        for (int i = 0; i < 4; i++) {
            int row = lrow + i * 32;
            const int m = m0 + row;
            const int b_ = m >> 11, t_ = m & 2047;
            uint32_t so = sb + s*36864 + row*144 + lc8*2;
            cp16(so, g_xh + (((size_t)b_*HH + cc)*TT + t_)*DKK + lc8);
            cp16(so + 18432, g_wo + (size_t)(n0+row)*512 + cc*64 + lc8);
        }
        cpcommit();
    };

    issue(0, 0);
    issue(1, 1);

    float acc[4][4][4] = {};

    for (int c = 0; c < 8; c++) {
        if (c < 7) cpwait<1>(); else cpwait<0>();
        __syncthreads();
        const __half* sA = (const __half*)(smn + (c & 1) * 36864);
        const __half* sB = sA + 9216;
        #pragma unroll
        for (int ks = 0; ks < 4; ks++) {
            const int k0 = ks * 16 + (lane & 3) * 2;
            uint32_t af[4][4], bf[4][2];
            #pragma unroll
            for (int mt = 0; mt < 4; mt++) {
                const __half* p = &sA[(wm*64 + mt*16 + (lane>>2))*72 + k0];
                af[mt][0] = *(const uint32_t*)p;
                af[mt][1] = *(const uint32_t*)(p + 8*72);
                af[mt][2] = *(const uint32_t*)(p + 8);
                af[mt][3] = *(const uint32_t*)(p + 8*72 + 8);
            }
            #pragma unroll
            for (int nt = 0; nt < 4; nt++) {
                const __half* p = &sB[(wn*32 + nt*8 + (lane>>2))*72 + k0];
                bf[nt][0] = *(const uint32_t*)p;
                bf[nt][1] = *(const uint32_t*)(p + 8);
            }
            #pragma unroll
            for (int mt = 0; mt < 4; mt++)
                #pragma unroll
                for (int nt = 0; nt < 4; nt++)
                    mma16(acc[mt][nt], af[mt], bf[nt]);
        }
        __syncthreads();
        if (c + 2 < 8) issue(c + 2, c & 1);
    }

    #pragma unroll
    for (int mt = 0; mt < 4; mt++) {
        const int m = m0 + wm*64 + mt*16 + (lane>>2);
        #pragma unroll
        for (int nt = 0; nt < 4; nt++) {
            const int nl = wn*32 + nt*8 + (lane&3)*2;
            float bx = sBias[nl], by = sBias[nl+1];
            *(float2*)(outp + (size_t)m*512 + n0 + nl) =
                make_float2(acc[mt][nt][0] + bx, acc[mt][nt][1] + by);
            *(float2*)(outp + (size_t)(m+8)*512 + n0 + nl) =
                make_float2(acc[mt][nt][2] + bx, acc[mt][nt][3] + by);
        }
    }
}

// =============================================================
// Fused attention, fp16 + cp.async. 2 CTAs/SM.
// smem: sQ@0(18432) sK0@18432 sK1@36864 sVt@55296(17408)
//       sP@72704(34816) sL@107520(512)  total 108032
// =============================================================
#define SQ_O 0
#define SK_O 18432
#define SVT_O 55296
#define SP_O 72704
#define SL_O 107520
#define ATT_SMEM 108032

__global__ __launch_bounds__(256, 2) void attn_mma_kernel(
    const int* __restrict__ mask, float* __restrict__ sig)
{
    extern __shared__ char smn[];
    __half* sQ  = (__half*)(smn + SQ_O);
    __half* sVt = (__half*)(smn + SVT_O);
    __half* sP  = (__half*)(smn + SP_O);
    float*  sL  = (float*)(smn + SL_O);
    const uint32_t sb = smem_u32(smn);

    const int tid = threadIdx.x;
    const int lane = tid & 31, wid = tid >> 5;
    const int wm = wid & 1,  wn = wid >> 1;   // S phase: 2x4
    const int wm2 = wid & 3, wn2 = wid >> 2;  // PV phase: 4x2
    const int bh = blockIdx.y;
    const int b_ = bh >> 3;
    const int q0 = blockIdx.x * 128;

    const __half* Qg = g_qh + (size_t)bh * TT * DKK;
    const __half* Kg = g_kh + (size_t)bh * TT * DKK;
    const __half* Vg = g_vh + (size_t)bh * DKK * TT;   // [dk][t]
    float* sigbh = sig + (size_t)bh * TT * TT;
    const int* maskb = mask + b_ * TT;

    if (tid < 128) sL[tid] = 0.0f;

    const int krow = tid >> 3, kc8 = (tid & 7) * 8;   // 128x64 tiles
    const int vdk = tid >> 4, vc8 = (tid & 15) * 8;   // 64x128 tile

    // G0: Q + K(0)
    #pragma unroll
    for (int i = 0; i < 4; i++) {
        int row = krow + i * 32;
        cp16(sb + SQ_O + row*144 + kc8*2, Qg + (size_t)(q0+row)*DKK + kc8);
        cp16(sb + SK_O + row*144 + kc8*2, Kg + (size_t)row*DKK + kc8);
    }
    cpcommit();

    float o[2][4][4] = {};
    float lsum[4][2] = {};

    for (int t = 0; t < 16; t++) {
        const int kv0 = t * 128;
        __syncthreads();   // PV(t-1) done with sVt/sP; sK[(t+1)&1] free

        // issue V(t) and K(t+1)  -> group G_{t+1}
        #pragma unroll
        for (int i = 0; i < 4; i++) {
            int dk = vdk + i * 16;
            cp16(sb + SVT_O + dk*272 + vc8*2, Vg + (size_t)dk*TT + kv0 + vc8);
        }
        if (t + 1 < 16) {
            const uint32_t kb = sb + SK_O + ((t+1) & 1) * 18432;
            #pragma unroll
            for (int i = 0; i < 4; i++) {
                int row = krow + i * 32;
                cp16(kb + row*144 + kc8*2, Kg + (size_t)(kv0+128+row)*DKK + kc8);
            }
        }
        cpcommit();

        cpwait<1>();       // K(t) arrived
        __syncthreads();

        const __half* sK = (const __half*)(smn + SK_O + (t & 1) * 18432);

        // S = Q @ K^T (two column halves) + epilogue
        #pragma unroll
        for (int hn = 0; hn < 2; hn++) {
            float s[4][2][4] = {};
            #pragma unroll
            for (int ks = 0; ks < 4; ks++) {
                const int k0 = ks * 16 + (lane & 3) * 2;
                uint32_t af[4][4], bf[2][2];
                #pragma unroll
                for (int mt = 0; mt < 4; mt++) {
                    const __half* p = &sQ[(wm*64 + mt*16 + (lane>>2))*72 + k0];
                    af[mt][0] = *(const uint32_t*)p;
                    af[mt][1] = *(const uint32_t*)(p + 8*72);
                    af[mt][2] = *(const uint32_t*)(p + 8);
                    af[mt][3] = *(const uint32_t*)(p + 8*72 + 8);
                }
                #pragma unroll
                for (int j = 0; j < 2; j++) {
                    const int nt = hn*2 + j;
                    const __half* p = &sK[(wn*32 + nt*8 + (lane>>2))*72 + k0];
                    bf[j][0] = *(const uint32_t*)p;
                    bf[j][1] = *(const uint32_t*)(p + 8);
                }
                #pragma unroll
                for (int mt = 0; mt < 4; mt++)
                    #pragma unroll
                    for (int j = 0; j < 2; j++)
                        mma16(s[mt][j], af[mt], bf[j]);
            }
            #pragma unroll
            for (int mt = 0; mt < 4; mt++) {
                const int r0 = wm*64 + mt*16 + (lane>>2);
                #pragma unroll
                for (int j = 0; j < 2; j++) {
                    const int cl = wn*32 + (hn*2+j)*8 + (lane&3)*2;
                    int2 mm = __ldg((const int2*)(maskb + kv0 + cl));
                    const float m0_ = mm.x ? 0.0f : -1e9f;
                    const float m1_ = mm.y ? 0.0f : -1e9f;
                    float s0 = s[mt][j][0]*0.125f + m0_;
                    float s1 = s[mt][j][1]*0.125f + m1_;
                    float s2 = s[mt][j][2]*0.125f + m0_;
                    float s3 = s[mt][j][3]*0.125f + m1_;
                    float p0 = __expf(s0), p1 = __expf(s1);
                    float p2 = __expf(s2), p3 = __expf(s3);
                    *(float2*)(sigbh + (size_t)(q0+r0)*TT + kv0 + cl) =
                        make_float2(__fdividef(p0, 1.0f+p0), __fdividef(p1, 1.0f+p1));
                    *(float2*)(sigbh + (size_t)(q0+r0+8)*TT + kv0 + cl) =
                        make_float2(__fdividef(p2, 1.0f+p2), __fdividef(p3, 1.0f+p3));
                    lsum[mt][0] += p0 + p1;
                    lsum[mt][1] += p2 + p3;
                    *(__half2*)&sP[r0*136 + cl]     = __floats2half2_rn(p0, p1);
                    *(__half2*)&sP[(r0+8)*136 + cl] = __floats2half2_rn(p2, p3);
                }
            }
        }

        cpwait<0>();       // V(t) arrived
        __syncthreads();   // sP + sVt visible

        // O += P @ V
        #pragma unroll
        for (int ks = 0; ks < 8; ks++) {
            const int k0 = ks * 16 + (lane & 3) * 2;
            uint32_t af[2][4], bf[4][2];
            #pragma unroll
            for (int mt = 0; mt < 2; mt++) {
                const __half* p = &sP[(wm2*32 + mt*16 + (lane>>2))*136 + k0];
                af[mt][0] = *(const uint32_t*)p;
                af[mt][1] = *(const uint32_t*)(p + 8*136);
                af[mt][2] = *(const uint32_t*)(p + 8);
                af[mt][3] = *(const uint32_t*)(p + 8*136 + 8);
            }
            #pragma unroll
            for (int nt = 0; nt < 4; nt++) {
                const __half* p = &sVt[(wn2*32 + nt*8 + (lane>>2))*136 + k0];
                bf[nt][0] = *(const uint32_t*)p;
                bf[nt][1] = *(const uint32_t*)(p + 8);
            }
            #pragma unroll
            for (int mt = 0; mt < 2; mt++)
                #pragma unroll
                for (int nt = 0; nt < 4; nt++)
                    mma16(o[mt][nt], af[mt], bf[nt]);
        }
    }

    // reduce row sums
    #pragma unroll
    for (int mt = 0; mt < 4; mt++)
        #pragma unroll
        for (int h = 0; h < 2; h++) {
            float v = lsum[mt][h];
            v += __shfl_xor_sync(0xffffffffu, v, 1);
            v += __shfl_xor_sync(0xffffffffu, v, 2);
            if ((lane & 3) == 0)
                atomicAdd(&sL[wm*64 + mt*16 + (lane>>2) + h*8], v);
        }
    __syncthreads();

    // normalize + store X (fp16)
    #pragma unroll
    for (int mt = 0; mt < 2; mt++) {
        const int r = wm2*32 + mt*16 + (lane>>2);
        const float li0 = 1.0f / sL[r];
        const float li1 = 1.0f / sL[r+8];
        #pragma unroll
        for (int nt = 0; nt < 4; nt++) {
            const int cc = wn2*32 + nt*8 + (lane&3)*2;
            *(__half2*)(g_xh + ((size_t)bh*TT + q0 + r)*DKK + cc) =
                __floats2half2_rn(o[mt][nt][0]*li0, o[mt][nt][1]*li0);
            *(__half2*)(g_xh + ((size_t)bh*TT + q0 + r + 8)*DKK + cc) =
                __floats2half2_rn(o[mt][nt][2]*li1, o[mt][nt][3]*li1);
        }
    }
}

// -------------------------------------------------------------
extern "C" void kernel_launch(void* const* d_in, const int* in_sizes, int n_in,
                              void* d_out, int out_size)
{
    const float* query = (const float*)d_in[0];
    const float* key   = (const float*)d_in[1];
    const float* value = (const float*)d_in[2];
    const int*   mask  = (const int*)d_in[3];
    const float* Wq = (const float*)d_in[4];
    const float* bq = (const float*)d_in[5];
    const float* Wk = (const float*)d_in[6];
    const float* bk = (const float*)d_in[7];
    const float* Wv = (const float*)d_in[8];
    const float* bv = (const float*)d_in[9];
    const float* Wo = (const float*)d_in[10];
    const float* bo = (const float*)d_in[11];

    float* out0 = (float*)d_out;                 // (B,T,D)
    float* sig  = out0 + (size_t)BB * TT * DD;   // (B,H,T,T)

    static bool configured = false;
    if (!configured) {
        cudaFuncSetAttribute(attn_mma_kernel,
            cudaFuncAttributeMaxDynamicSharedMemorySize, ATT_SMEM);
        cudaFuncSetAttribute(qkv_mma_kernel,
            cudaFuncAttributeMaxDynamicSharedMemorySize, PJ_SMEM);
        cudaFuncSetAttribute(oproj_mma_kernel,
            cudaFuncAttributeMaxDynamicSharedMemorySize, PJ_SMEM);
        configured = true;
    }

    cvt_kernel<<<13312, 256>>>(query, key, value, Wq, Wk, Wv, Wo);
    qkv_mma_kernel<<<dim3(4, 64, 3), 256, PJ_SMEM>>>(bq, bk, bv);
    attn_mma_kernel<<<dim3(16, 32), 256, ATT_SMEM>>>(mask, sig);
    oproj_mma_kernel<<<dim3(4, 64), 256, PJ_SMEM>>>(bo, out0);
}